// round 2
// baseline (speedup 1.0000x reference)
#include <cuda_runtime.h>
#include <cstdint>

#define MAXN 100000
#define BN_EPS 1e-5f

// ---------------- scratch (static device globals; no allocation) -------------
__device__ float  g_dis[MAXN];            // degree, then rsqrt(deg+1) in place
__device__ float4 g_h1[MAXN * 32];        // h1  [N,128]
__device__ float4 g_agg1[MAXN * 32];      // agg [N,128]
__device__ float4 g_h2[MAXN * 16];        // h2  [N,64]
__device__ float4 g_agg2[MAXN * 16];      // agg [N,64]
__device__ float2 g_h3[MAXN];             // h3  [N,2]
__device__ float  g_scale1[128], g_shift1[128];
__device__ float  g_scale2[64],  g_shift2[64];

// ---------------- helpers ----------------------------------------------------
__device__ __forceinline__ void red_add_v4(float4* p, float4 v) {
    asm volatile("red.global.add.v4.f32 [%0], {%1,%2,%3,%4};"
                 :: "l"(p), "f"(v.x), "f"(v.y), "f"(v.z), "f"(v.w) : "memory");
}
__device__ __forceinline__ void red_add_v2(float2* p, float a, float b) {
    asm volatile("red.global.add.v2.f32 [%0], {%1,%2};"
                 :: "l"(p), "f"(a), "f"(b) : "memory");
}

// ---------------- prep: BN scale/shift (bias folded in) ----------------------
__global__ void prep_kernel(const float* __restrict__ b1, const float* __restrict__ g1,
                            const float* __restrict__ be1, const float* __restrict__ m1,
                            const float* __restrict__ v1,
                            const float* __restrict__ b2, const float* __restrict__ g2,
                            const float* __restrict__ be2, const float* __restrict__ m2,
                            const float* __restrict__ v2) {
    int t = threadIdx.x;
    if (t < 128) {
        float s = g1[t] * rsqrtf(v1[t] + BN_EPS);
        g_scale1[t] = s;
        g_shift1[t] = fmaf(b1[t] - m1[t], s, be1[t]);
    }
    if (t < 64) {
        float s = g2[t] * rsqrtf(v2[t] + BN_EPS);
        g_scale2[t] = s;
        g_shift2[t] = fmaf(b2[t] - m2[t], s, be2[t]);
    }
}

__global__ void zero_deg_kernel(int N) {
    int i = blockIdx.x * blockDim.x + threadIdx.x;
    if (i < N) g_dis[i] = 0.f;
}

__global__ void deg_kernel(const int* __restrict__ ei, int E) {
    int e = blockIdx.x * blockDim.x + threadIdx.x;
    if (e < E) atomicAdd(&g_dis[ei[E + e]], 1.0f);
}

__global__ void dis_kernel(int N) {
    int i = blockIdx.x * blockDim.x + threadIdx.x;
    if (i < N) g_dis[i] = rsqrtf(g_dis[i] + 1.0f);
}

// ---------------- GEMM1: h1 = x@W1 ; agg1 = h1 * snorm -----------------------
// block 128 threads (one per output col), 64 rows per block, 4 rows/iter
__global__ void gemm1_kernel(const float* __restrict__ x, const float* __restrict__ W, int N) {
    __shared__ float Ws[64 * 128];
    __shared__ float xs[4][64];
    __shared__ float sn[4];
    const int tid = threadIdx.x;
    for (int i = tid; i < 64 * 128; i += 128) Ws[i] = W[i];
    const int row0 = blockIdx.x * 64;
    float* h1   = (float*)g_h1;
    float* agg1 = (float*)g_agg1;
    for (int rr = 0; rr < 64; rr += 4) {
        const int r = row0 + rr;
        __syncthreads();
        for (int i = tid; i < 256; i += 128) {
            int j = i >> 6, k = i & 63;
            int rowj = r + j;
            xs[j][k] = (rowj < N) ? x[(size_t)rowj * 64 + k] : 0.f;
        }
        if (tid < 4) {
            int rowj = r + tid;
            float d = (rowj < N) ? g_dis[rowj] : 0.f;
            sn[tid] = d * d;
        }
        __syncthreads();
        float a0 = 0.f, a1 = 0.f, a2 = 0.f, a3 = 0.f;
        #pragma unroll
        for (int k = 0; k < 64; k++) {
            float w = Ws[k * 128 + tid];
            a0 = fmaf(xs[0][k], w, a0);
            a1 = fmaf(xs[1][k], w, a1);
            a2 = fmaf(xs[2][k], w, a2);
            a3 = fmaf(xs[3][k], w, a3);
        }
        if (r + 3 < N) {
            size_t o = (size_t)r * 128 + tid;
            h1[o]       = a0; agg1[o]       = a0 * sn[0];
            h1[o + 128] = a1; agg1[o + 128] = a1 * sn[1];
            h1[o + 256] = a2; agg1[o + 256] = a2 * sn[2];
            h1[o + 384] = a3; agg1[o + 384] = a3 * sn[3];
        } else {
            float acc[4] = {a0, a1, a2, a3};
            for (int j = 0; j < 4; j++)
                if (r + j < N) {
                    size_t o = (size_t)(r + j) * 128 + tid;
                    h1[o] = acc[j]; agg1[o] = acc[j] * sn[j];
                }
        }
    }
}

// ---------------- scatter layer1: agg1[dst] += h1[src]*enorm (warp/edge) -----
__global__ void scatter1_kernel(const int* __restrict__ ei, int E) {
    int t = blockIdx.x * blockDim.x + threadIdx.x;
    int e = t >> 5;
    if (e >= E) return;
    int lane = t & 31;
    int src = ei[e], dst = ei[E + e];
    float w = g_dis[src] * g_dis[dst];
    float4 v = g_h1[src * 32 + lane];
    v.x *= w; v.y *= w; v.z *= w; v.w *= w;
    red_add_v4(&g_agg1[dst * 32 + lane], v);
}

// ---------------- fused: relu(bn(agg1)) @ W2 -> h2, agg2 = h2*snorm ----------
// block 64 threads (one per output col), 64 rows per block, 4 rows/iter
__global__ void fused2_kernel(const float* __restrict__ W2, int N) {
    __shared__ float Ws[128 * 64];
    __shared__ float zs[4][128];
    __shared__ float sc[128], sh[128];
    __shared__ float sn[4];
    const int tid = threadIdx.x;  // 64
    for (int i = tid; i < 128 * 64; i += 64) Ws[i] = W2[i];
    for (int i = tid; i < 128; i += 64) { sc[i] = g_scale1[i]; sh[i] = g_shift1[i]; }
    const float* agg1 = (const float*)g_agg1;
    float* h2   = (float*)g_h2;
    float* agg2 = (float*)g_agg2;
    const int row0 = blockIdx.x * 64;
    for (int rr = 0; rr < 64; rr += 4) {
        const int r = row0 + rr;
        __syncthreads();
        for (int i = tid; i < 512; i += 64) {
            int j = i >> 7, k = i & 127;
            int rowj = r + j;
            float v = (rowj < N) ? agg1[(size_t)rowj * 128 + k] : 0.f;
            zs[j][k] = fmaxf(fmaf(v, sc[k], sh[k]), 0.f);
        }
        if (tid < 4) {
            int rowj = r + tid;
            float d = (rowj < N) ? g_dis[rowj] : 0.f;
            sn[tid] = d * d;
        }
        __syncthreads();
        float a0 = 0.f, a1 = 0.f, a2 = 0.f, a3 = 0.f;
        #pragma unroll
        for (int k = 0; k < 128; k++) {
            float w = Ws[k * 64 + tid];
            a0 = fmaf(zs[0][k], w, a0);
            a1 = fmaf(zs[1][k], w, a1);
            a2 = fmaf(zs[2][k], w, a2);
            a3 = fmaf(zs[3][k], w, a3);
        }
        if (r + 3 < N) {
            size_t o = (size_t)r * 64 + tid;
            h2[o]       = a0; agg2[o]       = a0 * sn[0];
            h2[o + 64]  = a1; agg2[o + 64]  = a1 * sn[1];
            h2[o + 128] = a2; agg2[o + 128] = a2 * sn[2];
            h2[o + 192] = a3; agg2[o + 192] = a3 * sn[3];
        } else {
            float acc[4] = {a0, a1, a2, a3};
            for (int j = 0; j < 4; j++)
                if (r + j < N) {
                    size_t o = (size_t)(r + j) * 64 + tid;
                    h2[o] = acc[j]; agg2[o] = acc[j] * sn[j];
                }
        }
    }
}

// ---------------- scatter layer2: 16 lanes/edge ------------------------------
__global__ void scatter2_kernel(const int* __restrict__ ei, int E) {
    int t = blockIdx.x * blockDim.x + threadIdx.x;
    int e = t >> 4;
    if (e >= E) return;
    int lane = t & 15;
    int src = ei[e], dst = ei[E + e];
    float w = g_dis[src] * g_dis[dst];
    float4 v = g_h2[src * 16 + lane];
    v.x *= w; v.y *= w; v.z *= w; v.w *= w;
    red_add_v4(&g_agg2[dst * 16 + lane], v);
}

// ---------------- fused: relu(bn(agg2)) @ W3 -> h3; out init -----------------
// warp per row, 8 rows per 256-thread block
__global__ void fused3_kernel(const float* __restrict__ W3, const float* __restrict__ b3,
                              int N, float2* __restrict__ out) {
    __shared__ float W3s[128];
    __shared__ float sc[64], sh[64];
    int tid = threadIdx.x;  // 256
    if (tid < 128) W3s[tid] = W3[tid];
    if (tid < 64) { sc[tid] = g_scale2[tid]; sh[tid] = g_shift2[tid]; }
    __syncthreads();
    int lane = tid & 31, warp = tid >> 5;
    int r = blockIdx.x * 8 + warp;
    if (r >= N) return;
    const float* agg2 = (const float*)g_agg2;
    float v0 = agg2[(size_t)r * 64 + lane];
    float v1 = agg2[(size_t)r * 64 + lane + 32];
    float z0 = fmaxf(fmaf(v0, sc[lane], sh[lane]), 0.f);
    float z1 = fmaxf(fmaf(v1, sc[lane + 32], sh[lane + 32]), 0.f);
    float s0 = fmaf(z0, W3s[lane * 2 + 0], z1 * W3s[(lane + 32) * 2 + 0]);
    float s1 = fmaf(z0, W3s[lane * 2 + 1], z1 * W3s[(lane + 32) * 2 + 1]);
    #pragma unroll
    for (int off = 16; off; off >>= 1) {
        s0 += __shfl_down_sync(0xffffffffu, s0, off);
        s1 += __shfl_down_sync(0xffffffffu, s1, off);
    }
    if (lane == 0) {
        float d = g_dis[r];
        float snm = d * d;
        g_h3[r] = make_float2(s0, s1);
        out[r] = make_float2(fmaf(s0, snm, b3[0]), fmaf(s1, snm, b3[1]));
    }
}

// ---------------- scatter layer3: thread per edge into d_out -----------------
__global__ void scatter3_kernel(const int* __restrict__ ei, int E,
                                float2* __restrict__ out) {
    int e = blockIdx.x * blockDim.x + threadIdx.x;
    if (e >= E) return;
    int src = ei[e], dst = ei[E + e];
    float w = g_dis[src] * g_dis[dst];
    float2 v = g_h3[src];
    red_add_v2(&out[dst], v.x * w, v.y * w);
}

// ---------------- launch ------------------------------------------------------
extern "C" void kernel_launch(void* const* d_in, const int* in_sizes, int n_in,
                              void* d_out, int out_size) {
    const float* x   = (const float*)d_in[0];
    const int*   ei  = (const int*)d_in[1];
    const float* W1  = (const float*)d_in[2];
    const float* b1  = (const float*)d_in[3];
    const float* g1  = (const float*)d_in[4];
    const float* be1 = (const float*)d_in[5];
    const float* m1  = (const float*)d_in[6];
    const float* v1  = (const float*)d_in[7];
    const float* W2  = (const float*)d_in[8];
    const float* b2  = (const float*)d_in[9];
    const float* g2  = (const float*)d_in[10];
    const float* be2 = (const float*)d_in[11];
    const float* m2  = (const float*)d_in[12];
    const float* v2  = (const float*)d_in[13];
    const float* W3  = (const float*)d_in[14];
    const float* b3  = (const float*)d_in[15];

    const int N = in_sizes[0] / 64;
    const int E = in_sizes[1] / 2;
    float2* out = (float2*)d_out;

    prep_kernel<<<1, 128>>>(b1, g1, be1, m1, v1, b2, g2, be2, m2, v2);
    zero_deg_kernel<<<(N + 255) / 256, 256>>>(N);
    deg_kernel<<<(E + 255) / 256, 256>>>(ei, E);
    dis_kernel<<<(N + 255) / 256, 256>>>(N);

    gemm1_kernel<<<(N + 63) / 64, 128>>>(x, W1, N);
    scatter1_kernel<<<(E * 32 + 255) / 256, 256>>>(ei, E);

    fused2_kernel<<<(N + 63) / 64, 64>>>(W2, N);
    scatter2_kernel<<<(E * 16 + 255) / 256, 256>>>(ei, E);

    fused3_kernel<<<(N + 7) / 8, 256>>>(W3, b3, N, out);
    scatter3_kernel<<<(E + 255) / 256, 256>>>(ei, E, out);
}

// round 3
// speedup vs baseline: 1.4751x; 1.4751x over previous
#include <cuda_runtime.h>
#include <cstdint>

#define MAXN 100000
#define MAXE 800000
#define BN_EPS 1e-5f

typedef unsigned long long ull;

// ---------------- scratch ----------------------------------------------------
__device__ int   g_cnt[MAXN];          // in-degree (without self loop)
__device__ int   g_start[MAXN];        // CSR row start
__device__ int   g_cursor[MAXN];       // fill cursor
__device__ int   g_csr[MAXE];          // src indices grouped by dst
__device__ int   g_bsum[256], g_boff[256];
__device__ float g_dis[MAXN];          // rsqrt(deg+1)
__device__ float g_h1s[MAXN * 128];    // h1 * dis[row]
__device__ float g_z1[MAXN * 128];     // relu(bn(agg1))
__device__ float g_h2s[MAXN * 64];     // h2 * dis[row]
__device__ float g_z2[MAXN * 64];      // relu(bn(agg2))
__device__ float2 g_h3s[MAXN];         // h3 * dis[row]
__device__ float g_scale1[128], g_shift1[128];
__device__ float g_scale2[64],  g_shift2[64];

// ---------------- f32x2 helpers ----------------------------------------------
__device__ __forceinline__ ull ffma2(ull a, ull b, ull c) {
    ull d; asm("fma.rn.f32x2 %0, %1, %2, %3;" : "=l"(d) : "l"(a), "l"(b), "l"(c));
    return d;
}
__device__ __forceinline__ ull pack2(float x, float y) {
    ull d; asm("mov.b64 %0, {%1,%2};" : "=l"(d) : "f"(x), "f"(y)); return d;
}
__device__ __forceinline__ float2 unpack2(ull v) {
    float2 r; asm("mov.b64 {%0,%1}, %2;" : "=f"(r.x), "=f"(r.y) : "l"(v)); return r;
}

// ---------------- prep: BN scale/shift (bias folded) --------------------------
__global__ void prep_kernel(const float* __restrict__ b1, const float* __restrict__ g1,
                            const float* __restrict__ be1, const float* __restrict__ m1,
                            const float* __restrict__ v1,
                            const float* __restrict__ b2, const float* __restrict__ g2,
                            const float* __restrict__ be2, const float* __restrict__ m2,
                            const float* __restrict__ v2) {
    int t = threadIdx.x;
    if (t < 128) {
        float s = g1[t] * rsqrtf(v1[t] + BN_EPS);
        g_scale1[t] = s;
        g_shift1[t] = fmaf(b1[t] - m1[t], s, be1[t]);
    }
    if (t < 64) {
        float s = g2[t] * rsqrtf(v2[t] + BN_EPS);
        g_scale2[t] = s;
        g_shift2[t] = fmaf(b2[t] - m2[t], s, be2[t]);
    }
}

// ---------------- CSR build ----------------------------------------------------
__global__ void zero_cnt_kernel(int N) {
    int i = blockIdx.x * blockDim.x + threadIdx.x;
    if (i < N) g_cnt[i] = 0;
}
__global__ void hist_kernel(const int* __restrict__ ei, int E) {
    int e = blockIdx.x * blockDim.x + threadIdx.x;
    if (e < E) atomicAdd(&g_cnt[ei[E + e]], 1);
}
// block-level partial sums + dis computation
__global__ void scan_part_kernel(int N) {
    __shared__ int sh[1024];
    int i = blockIdx.x * 1024 + threadIdx.x;
    int c = (i < N) ? g_cnt[i] : 0;
    if (i < N) g_dis[i] = rsqrtf((float)c + 1.0f);
    sh[threadIdx.x] = c; __syncthreads();
    for (int s = 512; s > 0; s >>= 1) {
        if (threadIdx.x < s) sh[threadIdx.x] += sh[threadIdx.x + s];
        __syncthreads();
    }
    if (threadIdx.x == 0) g_bsum[blockIdx.x] = sh[0];
}
__global__ void scan_top_kernel(int nb) {
    __shared__ int sh[256];
    int tid = threadIdx.x;
    int v = (tid < nb) ? g_bsum[tid] : 0;
    sh[tid] = v; __syncthreads();
    for (int s = 1; s < 256; s <<= 1) {
        int t = (tid >= s) ? sh[tid - s] : 0;
        __syncthreads();
        sh[tid] += t;
        __syncthreads();
    }
    if (tid < nb) g_boff[tid] = sh[tid] - v;
}
__global__ void scan_down_kernel(int N) {
    __shared__ int sh[1024];
    int tid = threadIdx.x;
    int i = blockIdx.x * 1024 + tid;
    int c = (i < N) ? g_cnt[i] : 0;
    sh[tid] = c; __syncthreads();
    for (int s = 1; s < 1024; s <<= 1) {
        int t = (tid >= s) ? sh[tid - s] : 0;
        __syncthreads();
        sh[tid] += t;
        __syncthreads();
    }
    if (i < N) {
        int start = g_boff[blockIdx.x] + sh[tid] - c;
        g_start[i] = start;
        g_cursor[i] = start;
    }
}
__global__ void fill_kernel(const int* __restrict__ ei, int E) {
    int e = blockIdx.x * blockDim.x + threadIdx.x;
    if (e >= E) return;
    int src = ei[e], dst = ei[E + e];
    int p = atomicAdd(&g_cursor[dst], 1);
    g_csr[p] = src;
}

// ---------------- GEMM1: h1s = (x @ W1) * dis[row] ---------------------------
// block 256 threads; tile 32 rows x 128 cols; thread = 4 rows x 4 cols (FFMA2)
__global__ __launch_bounds__(256) void gemm1_kernel(const float* __restrict__ x,
                                                    const float* __restrict__ W, int N) {
    __shared__ float Ws[64 * 128];   // 32KB
    __shared__ float xs[32][64];     // 8KB
    const int tid = threadIdx.x;
    const int row0 = blockIdx.x * 32;
    for (int i = tid; i < 64 * 128; i += 256) Ws[i] = W[i];
    for (int i = tid; i < 32 * 64; i += 256) {
        int r = i >> 6, k = i & 63;
        int gr = row0 + r;
        xs[r][k] = (gr < N) ? x[(size_t)gr * 64 + k] : 0.f;
    }
    __syncthreads();
    const int c4 = tid & 31;   // cols c4*4 .. +3
    const int r4 = tid >> 5;   // rows r4*4 .. +3
    ull acc[4][2];
    #pragma unroll
    for (int r = 0; r < 4; r++) { acc[r][0] = 0ull; acc[r][1] = 0ull; }
    #pragma unroll 16
    for (int k = 0; k < 64; k++) {
        ulonglong2 wv = *(const ulonglong2*)&Ws[k * 128 + c4 * 4];
        float x0 = xs[r4 * 4 + 0][k];
        float x1 = xs[r4 * 4 + 1][k];
        float x2 = xs[r4 * 4 + 2][k];
        float x3 = xs[r4 * 4 + 3][k];
        ull d0 = pack2(x0, x0), d1 = pack2(x1, x1), d2 = pack2(x2, x2), d3 = pack2(x3, x3);
        acc[0][0] = ffma2(d0, wv.x, acc[0][0]); acc[0][1] = ffma2(d0, wv.y, acc[0][1]);
        acc[1][0] = ffma2(d1, wv.x, acc[1][0]); acc[1][1] = ffma2(d1, wv.y, acc[1][1]);
        acc[2][0] = ffma2(d2, wv.x, acc[2][0]); acc[2][1] = ffma2(d2, wv.y, acc[2][1]);
        acc[3][0] = ffma2(d3, wv.x, acc[3][0]); acc[3][1] = ffma2(d3, wv.y, acc[3][1]);
    }
    #pragma unroll
    for (int r = 0; r < 4; r++) {
        int gr = row0 + r4 * 4 + r;
        if (gr < N) {
            float d = g_dis[gr];
            float2 p0 = unpack2(acc[r][0]), p1 = unpack2(acc[r][1]);
            float4 o = make_float4(p0.x * d, p0.y * d, p1.x * d, p1.y * d);
            *(float4*)&g_h1s[(size_t)gr * 128 + c4 * 4] = o;
        }
    }
}

// ---------------- agg1: z1 = relu(bn(dis[dst]*(sum h1s[src] + h1s[dst]))) ----
__global__ __launch_bounds__(256) void agg1_kernel(int N) {
    int gw = blockIdx.x * 8 + (threadIdx.x >> 5);
    int lane = threadIdx.x & 31;
    if (gw >= N) return;
    const float* base = g_h1s;
    float4 a0 = *(const float4*)&base[(size_t)gw * 128 + lane * 4];  // self
    float4 a1 = make_float4(0.f, 0.f, 0.f, 0.f);
    int s = g_start[gw];
    int e = s + g_cnt[gw];
    int j = s;
    for (; j + 1 < e; j += 2) {
        int i0 = g_csr[j], i1 = g_csr[j + 1];
        float4 v0 = *(const float4*)&base[(size_t)i0 * 128 + lane * 4];
        float4 v1 = *(const float4*)&base[(size_t)i1 * 128 + lane * 4];
        a0.x += v0.x; a0.y += v0.y; a0.z += v0.z; a0.w += v0.w;
        a1.x += v1.x; a1.y += v1.y; a1.z += v1.z; a1.w += v1.w;
    }
    if (j < e) {
        int i0 = g_csr[j];
        float4 v0 = *(const float4*)&base[(size_t)i0 * 128 + lane * 4];
        a0.x += v0.x; a0.y += v0.y; a0.z += v0.z; a0.w += v0.w;
    }
    float d = g_dis[gw];
    float4 sc = *(const float4*)&g_scale1[lane * 4];
    float4 sh = *(const float4*)&g_shift1[lane * 4];
    float4 z;
    z.x = fmaxf(fmaf((a0.x + a1.x) * d, sc.x, sh.x), 0.f);
    z.y = fmaxf(fmaf((a0.y + a1.y) * d, sc.y, sh.y), 0.f);
    z.z = fmaxf(fmaf((a0.z + a1.z) * d, sc.z, sh.z), 0.f);
    z.w = fmaxf(fmaf((a0.w + a1.w) * d, sc.w, sh.w), 0.f);
    *(float4*)&g_z1[(size_t)gw * 128 + lane * 4] = z;
}

// ---------------- GEMM2: h2s = (z1 @ W2) * dis[row] --------------------------
// block 256 threads; tile 32 rows x 64 cols; thread = 2 rows x 4 cols
__global__ __launch_bounds__(256) void gemm2_kernel(const float* __restrict__ W, int N) {
    __shared__ float Ws[128 * 64];   // 32KB
    __shared__ float zs[32][128];    // 16KB
    const int tid = threadIdx.x;
    const int row0 = blockIdx.x * 32;
    for (int i = tid; i < 128 * 64; i += 256) Ws[i] = W[i];
    for (int i = tid; i < 32 * 128; i += 256) {
        int r = i >> 7, k = i & 127;
        int gr = row0 + r;
        zs[r][k] = (gr < N) ? g_z1[(size_t)gr * 128 + k] : 0.f;
    }
    __syncthreads();
    const int c4 = tid & 15;   // cols c4*4 .. +3
    const int r2 = tid >> 4;   // rows r2*2 .. +1
    ull acc[2][2];
    acc[0][0] = acc[0][1] = acc[1][0] = acc[1][1] = 0ull;
    #pragma unroll 16
    for (int k = 0; k < 128; k++) {
        ulonglong2 wv = *(const ulonglong2*)&Ws[k * 64 + c4 * 4];
        float x0 = zs[r2 * 2 + 0][k];
        float x1 = zs[r2 * 2 + 1][k];
        ull d0 = pack2(x0, x0), d1 = pack2(x1, x1);
        acc[0][0] = ffma2(d0, wv.x, acc[0][0]); acc[0][1] = ffma2(d0, wv.y, acc[0][1]);
        acc[1][0] = ffma2(d1, wv.x, acc[1][0]); acc[1][1] = ffma2(d1, wv.y, acc[1][1]);
    }
    #pragma unroll
    for (int r = 0; r < 2; r++) {
        int gr = row0 + r2 * 2 + r;
        if (gr < N) {
            float d = g_dis[gr];
            float2 p0 = unpack2(acc[r][0]), p1 = unpack2(acc[r][1]);
            float4 o = make_float4(p0.x * d, p0.y * d, p1.x * d, p1.y * d);
            *(float4*)&g_h2s[(size_t)gr * 64 + c4 * 4] = o;
        }
    }
}

// ---------------- agg2: z2 = relu(bn(dis[dst]*(sum h2s[src] + h2s[dst]))) ----
__global__ __launch_bounds__(256) void agg2_kernel(int N) {
    int gw = blockIdx.x * 8 + (threadIdx.x >> 5);
    int lane = threadIdx.x & 31;
    if (gw >= N) return;
    const float* base = g_h2s;
    float2 a0 = *(const float2*)&base[(size_t)gw * 64 + lane * 2];  // self
    float2 a1 = make_float2(0.f, 0.f);
    int s = g_start[gw];
    int e = s + g_cnt[gw];
    int j = s;
    for (; j + 1 < e; j += 2) {
        int i0 = g_csr[j], i1 = g_csr[j + 1];
        float2 v0 = *(const float2*)&base[(size_t)i0 * 64 + lane * 2];
        float2 v1 = *(const float2*)&base[(size_t)i1 * 64 + lane * 2];
        a0.x += v0.x; a0.y += v0.y;
        a1.x += v1.x; a1.y += v1.y;
    }
    if (j < e) {
        int i0 = g_csr[j];
        float2 v0 = *(const float2*)&base[(size_t)i0 * 64 + lane * 2];
        a0.x += v0.x; a0.y += v0.y;
    }
    float d = g_dis[gw];
    float2 sc = *(const float2*)&g_scale2[lane * 2];
    float2 sh = *(const float2*)&g_shift2[lane * 2];
    float2 z;
    z.x = fmaxf(fmaf((a0.x + a1.x) * d, sc.x, sh.x), 0.f);
    z.y = fmaxf(fmaf((a0.y + a1.y) * d, sc.y, sh.y), 0.f);
    *(float2*)&g_z2[(size_t)gw * 64 + lane * 2] = z;
}

// ---------------- GEMV3: h3s = (z2 @ W3) * dis[row] --------------------------
__global__ __launch_bounds__(256) void gemv3_kernel(const float* __restrict__ W3, int N) {
    __shared__ float W3s[128];
    int tid = threadIdx.x;
    if (tid < 128) W3s[tid] = W3[tid];
    __syncthreads();
    int lane = tid & 31, w = tid >> 5;
    int r = blockIdx.x * 8 + w;
    if (r >= N) return;
    float z0 = g_z2[(size_t)r * 64 + lane];
    float z1 = g_z2[(size_t)r * 64 + lane + 32];
    float s0 = fmaf(z0, W3s[lane * 2 + 0], z1 * W3s[(lane + 32) * 2 + 0]);
    float s1 = fmaf(z0, W3s[lane * 2 + 1], z1 * W3s[(lane + 32) * 2 + 1]);
    #pragma unroll
    for (int off = 16; off; off >>= 1) {
        s0 += __shfl_down_sync(0xffffffffu, s0, off);
        s1 += __shfl_down_sync(0xffffffffu, s1, off);
    }
    if (lane == 0) {
        float d = g_dis[r];
        g_h3s[r] = make_float2(s0 * d, s1 * d);
    }
}

// ---------------- agg3: out = dis[dst]*(sum h3s[src] + h3s[dst]) + b3 --------
__global__ void agg3_kernel(const float* __restrict__ b3, int N, float2* __restrict__ out) {
    int i = blockIdx.x * blockDim.x + threadIdx.x;
    if (i >= N) return;
    float2 acc = g_h3s[i];
    int s = g_start[i];
    int e = s + g_cnt[i];
    for (int j = s; j < e; j++) {
        float2 v = g_h3s[g_csr[j]];
        acc.x += v.x; acc.y += v.y;
    }
    float d = g_dis[i];
    out[i] = make_float2(fmaf(acc.x, d, b3[0]), fmaf(acc.y, d, b3[1]));
}

// ---------------- launch -------------------------------------------------------
extern "C" void kernel_launch(void* const* d_in, const int* in_sizes, int n_in,
                              void* d_out, int out_size) {
    const float* x   = (const float*)d_in[0];
    const int*   ei  = (const int*)d_in[1];
    const float* W1  = (const float*)d_in[2];
    const float* b1  = (const float*)d_in[3];
    const float* g1  = (const float*)d_in[4];
    const float* be1 = (const float*)d_in[5];
    const float* m1  = (const float*)d_in[6];
    const float* v1  = (const float*)d_in[7];
    const float* W2  = (const float*)d_in[8];
    const float* b2  = (const float*)d_in[9];
    const float* g2  = (const float*)d_in[10];
    const float* be2 = (const float*)d_in[11];
    const float* m2  = (const float*)d_in[12];
    const float* v2  = (const float*)d_in[13];
    const float* W3  = (const float*)d_in[14];
    const float* b3  = (const float*)d_in[15];

    const int N = in_sizes[0] / 64;
    const int E = in_sizes[1] / 2;
    float2* out = (float2*)d_out;
    const int NB = (N + 1023) / 1024;

    prep_kernel<<<1, 128>>>(b1, g1, be1, m1, v1, b2, g2, be2, m2, v2);
    zero_cnt_kernel<<<(N + 255) / 256, 256>>>(N);
    hist_kernel<<<(E + 255) / 256, 256>>>(ei, E);
    scan_part_kernel<<<NB, 1024>>>(N);
    scan_top_kernel<<<1, 256>>>(NB);
    scan_down_kernel<<<NB, 1024>>>(N);
    fill_kernel<<<(E + 255) / 256, 256>>>(ei, E);

    gemm1_kernel<<<(N + 31) / 32, 256>>>(x, W1, N);
    agg1_kernel<<<(N + 7) / 8, 256>>>(N);

    gemm2_kernel<<<(N + 31) / 32, 256>>>(W2, N);
    agg2_kernel<<<(N + 7) / 8, 256>>>(N);

    gemv3_kernel<<<(N + 7) / 8, 256>>>(W3, N);
    agg3_kernel<<<(N + 255) / 256, 256>>>(b3, N, out);
}